// round 1
// baseline (speedup 1.0000x reference)
#include <cuda_runtime.h>
#include <math.h>

#define NN 100000
#define EE 1600000
#define F_IN 512
#define HH1 8
#define DD1 8
#define FF1 64      // HH1*DD1
#define HH2 1
#define DD2 40

// ---------------- scratch (static device globals; no allocation) ----------------
__device__ float g_hs1[NN * FF1];
__device__ float g_hd1[NN * FF1];
__device__ float g_p1[EE * HH1];     // logits, then p, then alpha (in place)
__device__ float g_m1[NN * HH1];
__device__ float g_s1[NN * HH1];
__device__ float g_h1[NN * FF1];     // layer-1 output, elu'd in place
__device__ float g_hs2[NN * DD2];
__device__ float g_hd2[NN * DD2];
__device__ float g_p2[EE * HH2];
__device__ float g_m2[NN * HH2];
__device__ float g_s2[NN * HH2];

// ---------------- helpers ----------------
__device__ __forceinline__ void atomicMaxF(float* addr, float v) {
    // Works with init = -inf. Positive values: int-max is monotone.
    // Negative values: uint-min is monotone (more negative => larger uint).
    // Mixed races resolve consistently to the float max.
    if (v >= 0.0f) atomicMax((int*)addr, __float_as_int(v));
    else           atomicMin((unsigned int*)addr, __float_as_uint(v));
}

__global__ void k_fill(float* p, int n, float v) {
    int i = blockIdx.x * blockDim.x + threadIdx.x;
    if (i < n) p[i] = v;
}

// ---------------- dual GEMM: C1 = A@W1 + b1, C2 = A@W2 + b2 ----------------
// A: [n, K] row-major. W: [K, M] row-major. blockDim = (64, 4). 32 rows/block.
__global__ void k_gemm_dual(const float* __restrict__ A, int K, int M,
                            const float* __restrict__ W1, const float* __restrict__ b1,
                            const float* __restrict__ W2, const float* __restrict__ b2,
                            float* __restrict__ C1, float* __restrict__ C2) {
    __shared__ float xs[32][16];
    __shared__ float w1s[16][64];
    __shared__ float w2s[16][64];
    const int tx = threadIdx.x;            // 0..63 : output column
    const int ty = threadIdx.y;            // 0..3  : row group
    const int tid = ty * 64 + tx;
    const int row0 = blockIdx.x * 32;

    float acc1[8], acc2[8];
#pragma unroll
    for (int r = 0; r < 8; r++) { acc1[r] = 0.f; acc2[r] = 0.f; }

    for (int kc = 0; kc < K; kc += 16) {
        // x tile: 32 rows x 16 k
        for (int i = tid; i < 32 * 16; i += 256) {
            int r = i >> 4, k = i & 15;
            xs[r][k] = A[(row0 + r) * K + kc + k];
        }
        // W tiles: 16 k x 64 cols (zero-pad cols >= M)
        for (int i = tid; i < 16 * 64; i += 256) {
            int k = i >> 6, c = i & 63;
            float v1 = 0.f, v2 = 0.f;
            if (c < M) { v1 = W1[(kc + k) * M + c]; v2 = W2[(kc + k) * M + c]; }
            w1s[k][c] = v1; w2s[k][c] = v2;
        }
        __syncthreads();
#pragma unroll
        for (int kk = 0; kk < 16; kk++) {
            float w1 = w1s[kk][tx], w2 = w2s[kk][tx];
#pragma unroll
            for (int r = 0; r < 8; r++) {
                float a = xs[ty * 8 + r][kk];
                acc1[r] = fmaf(a, w1, acc1[r]);
                acc2[r] = fmaf(a, w2, acc2[r]);
            }
        }
        __syncthreads();
    }

    if (tx < M) {
        float bb1 = b1[tx], bb2 = b2[tx];
#pragma unroll
        for (int r = 0; r < 8; r++) {
            int row = row0 + ty * 8 + r;
            C1[row * M + tx] = acc1[r] + bb1;
            C2[row * M + tx] = acc2[r] + bb2;
        }
    }
}

// ---------------- edge logits + segment max ----------------
template <int H, int D>
__global__ void k_logits(const float* __restrict__ hs, const float* __restrict__ hd,
                         const float* __restrict__ attn,
                         const int* __restrict__ src, const int* __restrict__ dst,
                         float* __restrict__ logits, float* __restrict__ m) {
    int idx = blockIdx.x * blockDim.x + threadIdx.x;
    if (idx >= EE * H) return;
    int e = idx / H, h = idx % H;
    int s = src[e], t = dst[e];
    const float4* a = reinterpret_cast<const float4*>(hs + (s * H + h) * D);
    const float4* b = reinterpret_cast<const float4*>(hd + (t * H + h) * D);
    const float4* w = reinterpret_cast<const float4*>(attn + h * D);
    float acc = 0.f;
#pragma unroll
    for (int i = 0; i < D / 4; i++) {
        float4 av = a[i], bv = b[i], wv = w[i];
        float x;
        x = av.x + bv.x; acc = fmaf((x > 0.f ? x : 0.2f * x), wv.x, acc);
        x = av.y + bv.y; acc = fmaf((x > 0.f ? x : 0.2f * x), wv.y, acc);
        x = av.z + bv.z; acc = fmaf((x > 0.f ? x : 0.2f * x), wv.z, acc);
        x = av.w + bv.w; acc = fmaf((x > 0.f ? x : 0.2f * x), wv.w, acc);
    }
    logits[idx] = acc;
    atomicMaxF(&m[t * H + h], acc);
}

// ---------------- exp(logit - m[dst]) + segment sum ----------------
template <int H>
__global__ void k_expsum(float* __restrict__ p, const float* __restrict__ m,
                         float* __restrict__ s, const int* __restrict__ dst) {
    int idx = blockIdx.x * blockDim.x + threadIdx.x;
    if (idx >= EE * H) return;
    int e = idx / H, h = idx % H;
    int t = dst[e];
    float v = __expf(p[idx] - m[t * H + h]);
    p[idx] = v;
    atomicAdd(&s[t * H + h], v);
}

// ---------------- alpha = p / (s[dst] + 1e-9) ----------------
template <int H>
__global__ void k_norm(float* __restrict__ p, const float* __restrict__ s,
                       const int* __restrict__ dst) {
    int idx = blockIdx.x * blockDim.x + threadIdx.x;
    if (idx >= EE * H) return;
    int e = idx / H, h = idx % H;
    int t = dst[e];
    p[idx] = p[idx] / (s[t * H + h] + 1e-9f);
}

// ---------------- out[dst] += alpha * hs[src] ----------------
template <int H, int D>
__global__ void k_scatter(const float* __restrict__ p, const float* __restrict__ hs,
                          const int* __restrict__ src, const int* __restrict__ dst,
                          float* __restrict__ out) {
    int idx = blockIdx.x * blockDim.x + threadIdx.x;
    if (idx >= EE * H * D) return;
    int e = idx / (H * D);
    int f = idx % (H * D);
    int h = f / D;
    int t = dst[e], s = src[e];
    float v = p[e * H + h] * hs[s * H * D + f];
    atomicAdd(&out[t * H * D + f], v);
}

__global__ void k_elu(float* __restrict__ x, int n) {
    int i = blockIdx.x * blockDim.x + threadIdx.x;
    if (i < n) {
        float v = x[i];
        x[i] = v > 0.f ? v : (__expf(v) - 1.f);
    }
}

// ---------------- launch ----------------
extern "C" void kernel_launch(void* const* d_in, const int* in_sizes, int n_in,
                              void* d_out, int out_size) {
    const float* x   = (const float*)d_in[0];
    const int*   src = (const int*)d_in[1];
    const int*   dst = (const int*)d_in[2];
    const float* W1s = (const float*)d_in[3];
    const float* b1s = (const float*)d_in[4];
    const float* W1d = (const float*)d_in[5];
    const float* b1d = (const float*)d_in[6];
    const float* a1  = (const float*)d_in[7];
    const float* W2s = (const float*)d_in[8];
    const float* b2s = (const float*)d_in[9];
    const float* W2d = (const float*)d_in[10];
    const float* b2d = (const float*)d_in[11];
    const float* a2  = (const float*)d_in[12];
    float* out = (float*)d_out;

    float *hs1, *hd1, *p1, *m1, *s1, *h1, *hs2, *hd2, *p2, *m2, *s2;
    cudaGetSymbolAddress((void**)&hs1, g_hs1);
    cudaGetSymbolAddress((void**)&hd1, g_hd1);
    cudaGetSymbolAddress((void**)&p1,  g_p1);
    cudaGetSymbolAddress((void**)&m1,  g_m1);
    cudaGetSymbolAddress((void**)&s1,  g_s1);
    cudaGetSymbolAddress((void**)&h1,  g_h1);
    cudaGetSymbolAddress((void**)&hs2, g_hs2);
    cudaGetSymbolAddress((void**)&hd2, g_hd2);
    cudaGetSymbolAddress((void**)&p2,  g_p2);
    cudaGetSymbolAddress((void**)&m2,  g_m2);
    cudaGetSymbolAddress((void**)&s2,  g_s2);

    const int T = 256;
    const float NEG_INF = -INFINITY;

    // init
    cudaMemsetAsync(s1, 0, NN * HH1 * sizeof(float));
    cudaMemsetAsync(h1, 0, NN * FF1 * sizeof(float));
    cudaMemsetAsync(s2, 0, NN * HH2 * sizeof(float));
    cudaMemsetAsync(out, 0, (size_t)NN * DD2 * sizeof(float));
    k_fill<<<(NN * HH1 + T - 1) / T, T>>>(m1, NN * HH1, NEG_INF);
    k_fill<<<(NN * HH2 + T - 1) / T, T>>>(m2, NN * HH2, NEG_INF);

    // ---- layer 1 ----
    k_gemm_dual<<<NN / 32, dim3(64, 4)>>>(x, F_IN, FF1, W1s, b1s, W1d, b1d, hs1, hd1);

    k_logits<HH1, DD1><<<(EE * HH1 + T - 1) / T, T>>>(hs1, hd1, a1, src, dst, p1, m1);
    k_expsum<HH1><<<(EE * HH1 + T - 1) / T, T>>>(p1, m1, s1, dst);
    k_norm<HH1><<<(EE * HH1 + T - 1) / T, T>>>(p1, s1, dst);
    k_scatter<HH1, DD1><<<(EE * FF1 + T - 1) / T, T>>>(p1, hs1, src, dst, h1);

    k_elu<<<(NN * FF1 + T - 1) / T, T>>>(h1, NN * FF1);

    // ---- layer 2 ----
    k_gemm_dual<<<NN / 32, dim3(64, 4)>>>(h1, FF1, DD2, W2s, b2s, W2d, b2d, hs2, hd2);

    k_logits<HH2, DD2><<<(EE * HH2 + T - 1) / T, T>>>(hs2, hd2, a2, src, dst, p2, m2);
    k_expsum<HH2><<<(EE * HH2 + T - 1) / T, T>>>(p2, m2, s2, dst);
    k_norm<HH2><<<(EE * HH2 + T - 1) / T, T>>>(p2, s2, dst);
    k_scatter<HH2, DD2><<<(EE * HH2 * DD2 + T - 1) / T, T>>>(p2, hs2, src, dst, out);
}

// round 3
// speedup vs baseline: 2.3933x; 2.3933x over previous
#include <cuda_runtime.h>
#include <math.h>

#define NN 100000
#define EE 1600000
#define F_IN 512
#define HH1 8
#define DD1 8
#define FF1 64
#define DD2 40

// ---------------- scratch ----------------
__device__ float g_hs1[NN * FF1];
__device__ float g_hd1[NN * FF1];
__device__ float g_p1[EE * HH1];
__device__ float g_s1[NN * HH1];
__device__ float g_h1[NN * FF1];
__device__ float g_hs2[NN * DD2];
__device__ float g_hd2[NN * DD2];
__device__ float g_p2[EE];
__device__ float g_s2[NN];

// ---------------- PTX helpers ----------------
__device__ __forceinline__ unsigned f2tf32(float f) {
    unsigned u;
    asm("cvt.rna.tf32.f32 %0, %1;" : "=r"(u) : "f"(f));
    return u;
}
__device__ __forceinline__ void redv4(float* addr, float a, float b, float c, float d) {
    asm volatile("red.global.add.v4.f32 [%0], {%1,%2,%3,%4};"
                 :: "l"(addr), "f"(a), "f"(b), "f"(c), "f"(d) : "memory");
}
__device__ __forceinline__ void red1(float* addr, float a) {
    asm volatile("red.global.add.f32 [%0], %1;" :: "l"(addr), "f"(a) : "memory");
}
__device__ __forceinline__ void mma_tf32(float* acc, const unsigned* a, const unsigned* b) {
    asm volatile(
        "mma.sync.aligned.m16n8k8.row.col.f32.tf32.tf32.f32 "
        "{%0,%1,%2,%3}, {%4,%5,%6,%7}, {%8,%9}, {%0,%1,%2,%3};"
        : "+f"(acc[0]), "+f"(acc[1]), "+f"(acc[2]), "+f"(acc[3])
        : "r"(a[0]), "r"(a[1]), "r"(a[2]), "r"(a[3]), "r"(b[0]), "r"(b[1]));
}

// ---------------- layer-1 GEMM: tf32 mma, dual weights concatenated ----------------
// C1 = A@W1 + b1 (cols 0..63), C2 = A@W2 + b2 (cols 64..127 of logical B)
// BM=128, BN=128, BK=16, 256 threads (8 warps, 2x4 grid), warp tile 64x32.
#define APAD 20
#define BPAD 132
__global__ __launch_bounds__(256, 1)
void k_gemm1_mma(const float* __restrict__ A,
                 const float* __restrict__ W1, const float* __restrict__ b1,
                 const float* __restrict__ W2, const float* __restrict__ b2,
                 float* __restrict__ C1, float* __restrict__ C2) {
    __shared__ unsigned As[2][128 * APAD];
    __shared__ unsigned Bs[2][16 * BPAD];

    const int tid = threadIdx.x;
    const int lane = tid & 31;
    const int warp = tid >> 5;
    const int wr = warp & 1;        // 0..1 row
    const int wc = warp >> 1;       // 0..3 col
    const int g = lane >> 2;        // 0..7
    const int tg = lane & 3;        // 0..3
    const int row0 = blockIdx.x * 128;

    float acc[4][4][4];
#pragma unroll
    for (int mi = 0; mi < 4; mi++)
#pragma unroll
        for (int ni = 0; ni < 4; ni++)
#pragma unroll
            for (int r = 0; r < 4; r++) acc[mi][ni][r] = 0.f;

    // staging regs
    float4 aR[2], bR[2];

    // index precompute for A loads: two float4 per thread
    const int fA0 = tid, fA1 = tid + 256;
    const int rA0 = fA0 >> 2, qA0 = fA0 & 3;
    const int rA1 = fA1 >> 2, qA1 = fA1 & 3;
    // B loads
    const int kB0 = fA0 >> 5, cB0 = (fA0 & 31) * 4;
    const int kB1 = fA1 >> 5, cB1 = (fA1 & 31) * 4;

    auto loadA = [&](int kc) {
        int r0g = row0 + rA0, r1g = row0 + rA1;
        aR[0] = (r0g < NN) ? *reinterpret_cast<const float4*>(A + (size_t)r0g * F_IN + kc + qA0 * 4)
                           : make_float4(0.f, 0.f, 0.f, 0.f);
        aR[1] = (r1g < NN) ? *reinterpret_cast<const float4*>(A + (size_t)r1g * F_IN + kc + qA1 * 4)
                           : make_float4(0.f, 0.f, 0.f, 0.f);
    };
    auto loadB = [&](int kc) {
        const float* s0 = (cB0 < 64) ? (W1 + (kc + kB0) * 64 + cB0) : (W2 + (kc + kB0) * 64 + cB0 - 64);
        const float* s1 = (cB1 < 64) ? (W1 + (kc + kB1) * 64 + cB1) : (W2 + (kc + kB1) * 64 + cB1 - 64);
        bR[0] = *reinterpret_cast<const float4*>(s0);
        bR[1] = *reinterpret_cast<const float4*>(s1);
    };
    auto storeA = [&](int buf) {
        uint4 u0 = make_uint4(f2tf32(aR[0].x), f2tf32(aR[0].y), f2tf32(aR[0].z), f2tf32(aR[0].w));
        uint4 u1 = make_uint4(f2tf32(aR[1].x), f2tf32(aR[1].y), f2tf32(aR[1].z), f2tf32(aR[1].w));
        *reinterpret_cast<uint4*>(&As[buf][rA0 * APAD + qA0 * 4]) = u0;
        *reinterpret_cast<uint4*>(&As[buf][rA1 * APAD + qA1 * 4]) = u1;
    };
    auto storeB = [&](int buf) {
        uint4 u0 = make_uint4(f2tf32(bR[0].x), f2tf32(bR[0].y), f2tf32(bR[0].z), f2tf32(bR[0].w));
        uint4 u1 = make_uint4(f2tf32(bR[1].x), f2tf32(bR[1].y), f2tf32(bR[1].z), f2tf32(bR[1].w));
        *reinterpret_cast<uint4*>(&Bs[buf][kB0 * BPAD + cB0]) = u0;
        *reinterpret_cast<uint4*>(&Bs[buf][kB1 * BPAD + cB1]) = u1;
    };

    loadA(0); loadB(0);
    storeA(0); storeB(0);
    int buf = 0;

    const int NITER = F_IN / 16;  // 32
    for (int it = 0; it < NITER; it++) {
        __syncthreads();
        if (it + 1 < NITER) { loadA((it + 1) * 16); loadB((it + 1) * 16); }

#pragma unroll
        for (int ks = 0; ks < 2; ks++) {
            const int k0 = ks * 8;
            unsigned afr[4][4], bfr[4][2];
#pragma unroll
            for (int mi = 0; mi < 4; mi++) {
                int base = wr * 64 + mi * 16;
                afr[mi][0] = As[buf][(base + g) * APAD + k0 + tg];
                afr[mi][1] = As[buf][(base + g + 8) * APAD + k0 + tg];
                afr[mi][2] = As[buf][(base + g) * APAD + k0 + tg + 4];
                afr[mi][3] = As[buf][(base + g + 8) * APAD + k0 + tg + 4];
            }
#pragma unroll
            for (int ni = 0; ni < 4; ni++) {
                int col = wc * 32 + ni * 8 + g;
                bfr[ni][0] = Bs[buf][(k0 + tg) * BPAD + col];
                bfr[ni][1] = Bs[buf][(k0 + tg + 4) * BPAD + col];
            }
#pragma unroll
            for (int mi = 0; mi < 4; mi++)
#pragma unroll
                for (int ni = 0; ni < 4; ni++)
                    mma_tf32(acc[mi][ni], afr[mi], bfr[ni]);
        }
        if (it + 1 < NITER) { storeA(buf ^ 1); storeB(buf ^ 1); buf ^= 1; }
    }

    // epilogue
    float* Cw = (wc < 2) ? C1 : C2;
    const float* bw = (wc < 2) ? b1 : b2;
    const int cbase = (wc < 2) ? wc * 32 : (wc - 2) * 32;
#pragma unroll
    for (int mi = 0; mi < 4; mi++) {
#pragma unroll
        for (int ni = 0; ni < 4; ni++) {
            int col = cbase + ni * 8 + 2 * tg;
            float bb0 = __ldg(bw + col), bb1 = __ldg(bw + col + 1);
            int r0 = row0 + wr * 64 + mi * 16 + g;
            int r1 = r0 + 8;
            if (r0 < NN) {
                float2 v = make_float2(acc[mi][ni][0] + bb0, acc[mi][ni][1] + bb1);
                *reinterpret_cast<float2*>(Cw + (size_t)r0 * 64 + col) = v;
            }
            if (r1 < NN) {
                float2 v = make_float2(acc[mi][ni][2] + bb0, acc[mi][ni][3] + bb1);
                *reinterpret_cast<float2*>(Cw + (size_t)r1 * 64 + col) = v;
            }
        }
    }
}

// ---------------- layer-2 GEMM (FFMA, small) with fused ELU on A load ----------------
template <bool ELU>
__global__ void k_gemm_dual(const float* __restrict__ A, int K, int M,
                            const float* __restrict__ W1, const float* __restrict__ b1,
                            const float* __restrict__ W2, const float* __restrict__ b2,
                            float* __restrict__ C1, float* __restrict__ C2) {
    __shared__ float xs[32][16];
    __shared__ float w1s[16][64];
    __shared__ float w2s[16][64];
    const int tx = threadIdx.x;
    const int ty = threadIdx.y;
    const int tid = ty * 64 + tx;
    const int row0 = blockIdx.x * 32;

    float acc1[8], acc2[8];
#pragma unroll
    for (int r = 0; r < 8; r++) { acc1[r] = 0.f; acc2[r] = 0.f; }

    for (int kc = 0; kc < K; kc += 16) {
        for (int i = tid; i < 32 * 16; i += 256) {
            int r = i >> 4, k = i & 15;
            float v = A[(row0 + r) * K + kc + k];
            if (ELU) v = v > 0.f ? v : (__expf(v) - 1.f);
            xs[r][k] = v;
        }
        for (int i = tid; i < 16 * 64; i += 256) {
            int k = i >> 6, c = i & 63;
            float v1 = 0.f, v2 = 0.f;
            if (c < M) { v1 = W1[(kc + k) * M + c]; v2 = W2[(kc + k) * M + c]; }
            w1s[k][c] = v1; w2s[k][c] = v2;
        }
        __syncthreads();
#pragma unroll
        for (int kk = 0; kk < 16; kk++) {
            float w1 = w1s[kk][tx], w2 = w2s[kk][tx];
#pragma unroll
            for (int r = 0; r < 8; r++) {
                float a = xs[ty * 8 + r][kk];
                acc1[r] = fmaf(a, w1, acc1[r]);
                acc2[r] = fmaf(a, w2, acc2[r]);
            }
        }
        __syncthreads();
    }

    if (tx < M) {
        float bb1 = b1[tx], bb2 = b2[tx];
#pragma unroll
        for (int r = 0; r < 8; r++) {
            int row = row0 + ty * 8 + r;
            C1[row * M + tx] = acc1[r] + bb1;
            C2[row * M + tx] = acc2[r] + bb2;
        }
    }
}

// ---------------- layer 1 edges: logit -> exp -> segment-sum (no max pass) --------
__global__ void k_edge1(const float* __restrict__ hs, const float* __restrict__ hd,
                        const float* __restrict__ attn,
                        const int* __restrict__ src, const int* __restrict__ dst,
                        float* __restrict__ p, float* __restrict__ s) {
    int idx = blockIdx.x * blockDim.x + threadIdx.x;   // EE*8 exact
    int e = idx >> 3, h = idx & 7;
    int sn = __ldg(src + e), tn = __ldg(dst + e);
    const float4* a = reinterpret_cast<const float4*>(hs + (size_t)sn * 64 + h * 8);
    const float4* b = reinterpret_cast<const float4*>(hd + (size_t)tn * 64 + h * 8);
    const float4* w = reinterpret_cast<const float4*>(attn + h * 8);
    float accv = 0.f;
#pragma unroll
    for (int i = 0; i < 2; i++) {
        float4 av = a[i], bv = b[i], wv = __ldg(&w[i]);
        float x;
        x = av.x + bv.x; accv = fmaf((x > 0.f ? x : 0.2f * x), wv.x, accv);
        x = av.y + bv.y; accv = fmaf((x > 0.f ? x : 0.2f * x), wv.y, accv);
        x = av.z + bv.z; accv = fmaf((x > 0.f ? x : 0.2f * x), wv.z, accv);
        x = av.w + bv.w; accv = fmaf((x > 0.f ? x : 0.2f * x), wv.w, accv);
    }
    float pv = __expf(accv);
    p[idx] = pv;
    // aggregate 4 lanes (same dst row) into one vector RED
    float p1v = __shfl_down_sync(0xffffffffu, pv, 1);
    float p2v = __shfl_down_sync(0xffffffffu, pv, 2);
    float p3v = __shfl_down_sync(0xffffffffu, pv, 3);
    if ((h & 3) == 0)
        redv4(s + (size_t)tn * 8 + h, pv, p1v, p2v, p3v);
}

// ---------------- inv: x = 1/(x + 1e-9) ----------------
__global__ void k_inv(float* __restrict__ s, int n) {
    int i = blockIdx.x * blockDim.x + threadIdx.x;
    if (i < n) s[i] = 1.0f / (s[i] + 1e-9f);
}

// ---------------- layer 1 scatter: h1[dst] += alpha * hs[src] (vector RED) -------
__global__ void k_scatter1(const float* __restrict__ p, const float* __restrict__ sinv,
                           const float* __restrict__ hs,
                           const int* __restrict__ src, const int* __restrict__ dst,
                           float* __restrict__ out) {
    int idx = blockIdx.x * blockDim.x + threadIdx.x;   // EE*8 exact
    int e = idx >> 3, h = idx & 7;
    int sn = __ldg(src + e), tn = __ldg(dst + e);
    float alpha = p[idx] * __ldg(sinv + (size_t)tn * 8 + h);
    const float4* u = reinterpret_cast<const float4*>(hs + (size_t)sn * 64 + h * 8);
    float4 u0 = u[0], u1 = u[1];
    float* o = out + (size_t)tn * 64 + h * 8;
    redv4(o, alpha * u0.x, alpha * u0.y, alpha * u0.z, alpha * u0.w);
    redv4(o + 4, alpha * u1.x, alpha * u1.y, alpha * u1.z, alpha * u1.w);
}

// ---------------- layer 2 edges: 8 threads per edge, D=40 ----------------
__global__ void k_edge2(const float* __restrict__ hs, const float* __restrict__ hd,
                        const float* __restrict__ attn,
                        const int* __restrict__ src, const int* __restrict__ dst,
                        float* __restrict__ p, float* __restrict__ s) {
    int idx = blockIdx.x * blockDim.x + threadIdx.x;   // EE*8 exact
    int e = idx >> 3, j = idx & 7;
    int sn = __ldg(src + e), tn = __ldg(dst + e);
    float part = 0.f;
#pragma unroll
    for (int rep = 0; rep < 2; rep++) {
        int c = j + rep * 8;
        if (c < 10) {
            float4 av = *reinterpret_cast<const float4*>(hs + (size_t)sn * 40 + c * 4);
            float4 bv = *reinterpret_cast<const float4*>(hd + (size_t)tn * 40 + c * 4);
            float4 wv = __ldg(reinterpret_cast<const float4*>(attn + c * 4));
            float x;
            x = av.x + bv.x; part = fmaf((x > 0.f ? x : 0.2f * x), wv.x, part);
            x = av.y + bv.y; part = fmaf((x > 0.f ? x : 0.2f * x), wv.y, part);
            x = av.z + bv.z; part = fmaf((x > 0.f ? x : 0.2f * x), wv.z, part);
            x = av.w + bv.w; part = fmaf((x > 0.f ? x : 0.2f * x), wv.w, part);
        }
    }
    part += __shfl_xor_sync(0xffffffffu, part, 4);
    part += __shfl_xor_sync(0xffffffffu, part, 2);
    part += __shfl_xor_sync(0xffffffffu, part, 1);
    if (j == 0) {
        float pv = __expf(part);
        p[e] = pv;
        red1(s + tn, pv);
    }
}

// ---------------- layer 2 scatter ----------------
__global__ void k_scatter2(const float* __restrict__ p, const float* __restrict__ sinv,
                           const float* __restrict__ hs,
                           const int* __restrict__ src, const int* __restrict__ dst,
                           float* __restrict__ out) {
    unsigned idx = blockIdx.x * blockDim.x + threadIdx.x;  // EE*10 exact
    unsigned e = idx / 10u;
    unsigned c = idx - e * 10u;
    int sn = __ldg(src + e), tn = __ldg(dst + e);
    float alpha = __ldg(p + e) * __ldg(sinv + tn);
    float4 u = *reinterpret_cast<const float4*>(hs + (size_t)sn * 40 + c * 4);
    redv4(out + (size_t)tn * 40 + c * 4, alpha * u.x, alpha * u.y, alpha * u.z, alpha * u.w);
}

// ---------------- launch ----------------
extern "C" void kernel_launch(void* const* d_in, const int* in_sizes, int n_in,
                              void* d_out, int out_size) {
    const float* x   = (const float*)d_in[0];
    const int*   src = (const int*)d_in[1];
    const int*   dst = (const int*)d_in[2];
    const float* W1s = (const float*)d_in[3];
    const float* b1s = (const float*)d_in[4];
    const float* W1d = (const float*)d_in[5];
    const float* b1d = (const float*)d_in[6];
    const float* a1  = (const float*)d_in[7];
    const float* W2s = (const float*)d_in[8];
    const float* b2s = (const float*)d_in[9];
    const float* W2d = (const float*)d_in[10];
    const float* b2d = (const float*)d_in[11];
    const float* a2  = (const float*)d_in[12];
    float* out = (float*)d_out;

    float *hs1, *hd1, *p1, *s1, *h1, *hs2, *hd2, *p2, *s2;
    cudaGetSymbolAddress((void**)&hs1, g_hs1);
    cudaGetSymbolAddress((void**)&hd1, g_hd1);
    cudaGetSymbolAddress((void**)&p1,  g_p1);
    cudaGetSymbolAddress((void**)&s1,  g_s1);
    cudaGetSymbolAddress((void**)&h1,  g_h1);
    cudaGetSymbolAddress((void**)&hs2, g_hs2);
    cudaGetSymbolAddress((void**)&hd2, g_hd2);
    cudaGetSymbolAddress((void**)&p2,  g_p2);
    cudaGetSymbolAddress((void**)&s2,  g_s2);

    const int T = 256;

    cudaMemsetAsync(s1, 0, NN * HH1 * sizeof(float));
    cudaMemsetAsync(h1, 0, (size_t)NN * FF1 * sizeof(float));
    cudaMemsetAsync(s2, 0, NN * sizeof(float));
    cudaMemsetAsync(out, 0, (size_t)NN * DD2 * sizeof(float));

    // ---- layer 1 ----
    k_gemm1_mma<<<(NN + 127) / 128, 256>>>(x, W1s, b1s, W1d, b1d, hs1, hd1);
    k_edge1<<<EE * HH1 / T, T>>>(hs1, hd1, a1, src, dst, p1, s1);
    k_inv<<<(NN * HH1 + T - 1) / T, T>>>(s1, NN * HH1);
    k_scatter1<<<EE * HH1 / T, T>>>(p1, s1, hs1, src, dst, h1);

    // ---- layer 2 (ELU fused into GEMM A-load) ----
    k_gemm_dual<true><<<NN / 32, dim3(64, 4)>>>(h1, FF1, DD2, W2s, b2s, W2d, b2d, hs2, hd2);
    k_edge2<<<EE * 8 / T, T>>>(hs2, hd2, a2, src, dst, p2, s2);
    k_inv<<<(NN + T - 1) / T, T>>>(s2, NN);
    k_scatter2<<<EE * 10 / T, T>>>(p2, s2, hs2, src, dst, out);
}